// round 3
// baseline (speedup 1.0000x reference)
#include <cuda_runtime.h>

// Problem constants
#define B_   2
#define S_   2048
#define H_   2048
#define NH_  16
#define HD_  128
#define M_   (B_ * S_)    // 4096 rows for the big GEMMs
#define BH_  (B_ * NH_)   // 32 (batch*heads)

// Scratch (device globals: allocation-free per harness rules)
__device__ float g_q[(size_t)BH_ * S_ * HD_];      //  32 MB
__device__ float g_k[(size_t)BH_ * S_ * HD_];      //  32 MB
__device__ float g_v[(size_t)BH_ * S_ * HD_];      //  32 MB
__device__ float g_attn[(size_t)BH_ * S_ * HD_];   //  32 MB
__device__ float g_scores[(size_t)BH_ * S_ * S_];  // 512 MB

// ---------------------------------------------------------------------------
// Shared GEMM micro-kernel pieces: 128x128 tile, BK=16, 256 threads,
// 8x8 per-thread accumulators.
// ---------------------------------------------------------------------------

__device__ __forceinline__ void store_a_frag(float As[16][128], int acol, int arow,
                                             float4 a0, float4 a1) {
    As[acol + 0][arow] = a0.x; As[acol + 1][arow] = a0.y;
    As[acol + 2][arow] = a0.z; As[acol + 3][arow] = a0.w;
    As[acol + 4][arow] = a1.x; As[acol + 5][arow] = a1.y;
    As[acol + 6][arow] = a1.z; As[acol + 7][arow] = a1.w;
}

__device__ __forceinline__ void store_b_frag(float Bs[16][128], int brow, int bcol,
                                             float4 b0, float4 b1) {
    *(float4*)&Bs[brow][bcol]     = b0;
    *(float4*)&Bs[brow][bcol + 4] = b1;
}

__device__ __forceinline__ void mma_tile(const float As[16][128], const float Bs[16][128],
                                         int ty, int tx, float acc[8][8]) {
#pragma unroll
    for (int kt = 0; kt < 16; ++kt) {
        float ar[8], br[8];
#pragma unroll
        for (int i = 0; i < 8; ++i) ar[i] = As[kt][ty * 8 + i];
#pragma unroll
        for (int j = 0; j < 8; ++j) br[j] = Bs[kt][tx * 8 + j];
#pragma unroll
        for (int i = 0; i < 8; ++i)
#pragma unroll
            for (int j = 0; j < 8; ++j)
                acc[i][j] += ar[i] * br[j];
    }
}

// ---------------------------------------------------------------------------
// Kernel 1: QKV projections. grid = (H/128, M/128, 3), z selects Q/K/V.
// Out layout: [B, NH, S, HD]  (head-major for attention).
// ---------------------------------------------------------------------------
__global__ __launch_bounds__(256, 2)
void qkv_kernel(const float* __restrict__ x,
                const float* __restrict__ wq, const float* __restrict__ bq,
                const float* __restrict__ wk, const float* __restrict__ bk,
                const float* __restrict__ wv, const float* __restrict__ bv) {
    const float* W; const float* bias; float* out;
    int z = blockIdx.z;
    if (z == 0)      { W = wq; bias = bq; out = g_q; }
    else if (z == 1) { W = wk; bias = bk; out = g_k; }
    else             { W = wv; bias = bv; out = g_v; }

    __shared__ float As[16][128];
    __shared__ float Bs[16][128];

    const int tid = threadIdx.x;
    const int ty = tid >> 4, tx = tid & 15;
    const int m0 = blockIdx.y * 128, n0 = blockIdx.x * 128;
    const int arow = tid >> 1, acol = (tid & 1) * 8;
    const int brow = tid >> 4, bcol = (tid & 15) * 8;

    float acc[8][8];
#pragma unroll
    for (int i = 0; i < 8; ++i)
#pragma unroll
        for (int j = 0; j < 8; ++j) acc[i][j] = 0.0f;

    const float* aptr = x + (size_t)(m0 + arow) * H_ + acol;
    const float* bptr = W + (size_t)brow * H_ + n0 + bcol;

    float4 a0 = *(const float4*)(aptr);
    float4 a1 = *(const float4*)(aptr + 4);
    float4 b0 = *(const float4*)(bptr);
    float4 b1 = *(const float4*)(bptr + 4);

    for (int k0 = 0; k0 < H_; k0 += 16) {
        store_a_frag(As, acol, arow, a0, a1);
        store_b_frag(Bs, brow, bcol, b0, b1);
        __syncthreads();
        if (k0 + 16 < H_) {
            a0 = *(const float4*)(aptr + k0 + 16);
            a1 = *(const float4*)(aptr + k0 + 20);
            b0 = *(const float4*)(bptr + (size_t)(k0 + 16) * H_);
            b1 = *(const float4*)(bptr + (size_t)(k0 + 16) * H_ + 4);
        }
        mma_tile(As, Bs, ty, tx, acc);
        __syncthreads();
    }

    const int h = blockIdx.x;  // H/128 == NH so block-col == head
#pragma unroll
    for (int i = 0; i < 8; ++i) {
        int m = m0 + ty * 8 + i;
        int b = m >> 11, s = m & (S_ - 1);
        float* orow = out + ((size_t)(b * NH_ + h) * S_ + s) * HD_;
#pragma unroll
        for (int j = 0; j < 8; ++j) {
            int d = tx * 8 + j;
            orow[d] = acc[i][j] + bias[h * HD_ + d];
        }
    }
}

// ---------------------------------------------------------------------------
// Kernel 2: scores = (Q @ K^T) * scale + mask. grid = (S/128, S/128, BH).
// ---------------------------------------------------------------------------
__global__ __launch_bounds__(256, 2)
void scores_kernel(const float* __restrict__ mask) {
    const int z = blockIdx.z;
    const float* Q = g_q + (size_t)z * S_ * HD_;
    const float* K = g_k + (size_t)z * S_ * HD_;

    __shared__ float As[16][128];
    __shared__ float Bs[16][128];

    const int tid = threadIdx.x;
    const int ty = tid >> 4, tx = tid & 15;
    const int q0 = blockIdx.y * 128, n0 = blockIdx.x * 128;
    const int arow = tid >> 1, acol = (tid & 1) * 8;  // A loader
    const int nrow = tid >> 1, kq   = (tid & 1) * 8;  // B loader (transposed)

    float acc[8][8];
#pragma unroll
    for (int i = 0; i < 8; ++i)
#pragma unroll
        for (int j = 0; j < 8; ++j) acc[i][j] = 0.0f;

    const float* aptr = Q + (size_t)(q0 + arow) * HD_ + acol;
    const float* bptr = K + (size_t)(n0 + nrow) * HD_ + kq;

    float4 a0 = *(const float4*)(aptr);
    float4 a1 = *(const float4*)(aptr + 4);
    float4 b0 = *(const float4*)(bptr);
    float4 b1 = *(const float4*)(bptr + 4);

    for (int k0 = 0; k0 < HD_; k0 += 16) {
        store_a_frag(As, acol, arow, a0, a1);
        store_a_frag(Bs, kq, nrow, b0, b1);  // transposed store: Bs[k][n]
        __syncthreads();
        if (k0 + 16 < HD_) {
            a0 = *(const float4*)(aptr + k0 + 16);
            a1 = *(const float4*)(aptr + k0 + 20);
            b0 = *(const float4*)(bptr + k0 + 16);
            b1 = *(const float4*)(bptr + k0 + 20);
        }
        mma_tile(As, Bs, ty, tx, acc);
        __syncthreads();
    }

    const float scale = 0.08838834764831845f;  // 1/sqrt(128)
    const int b = z >> 4;
    float* srow_base = g_scores + (size_t)z * S_ * S_;
#pragma unroll
    for (int i = 0; i < 8; ++i) {
        int q = q0 + ty * 8 + i;
        const float* mrow = mask + ((size_t)b * S_ + q) * S_;
        float* srow = srow_base + (size_t)q * S_;
#pragma unroll
        for (int j = 0; j < 8; ++j) {
            int kc = n0 + tx * 8 + j;
            srow[kc] = acc[i][j] * scale + mrow[kc];
        }
    }
}

// ---------------------------------------------------------------------------
// Kernel 3: row softmax over S=2048. grid = (S, BH), 256 threads, 8 elts/thread.
// ---------------------------------------------------------------------------
__global__ __launch_bounds__(256)
void softmax_kernel() {
    const int q = blockIdx.x, z = blockIdx.y;
    float* row = g_scores + ((size_t)z * S_ + q) * S_;
    const int t = threadIdx.x;
    const int warp = t >> 5, lane = t & 31;

    float x[8];
#pragma unroll
    for (int i = 0; i < 8; ++i) x[i] = row[t + 256 * i];

    float m = x[0];
#pragma unroll
    for (int i = 1; i < 8; ++i) m = fmaxf(m, x[i]);
#pragma unroll
    for (int off = 16; off; off >>= 1) m = fmaxf(m, __shfl_xor_sync(0xffffffffu, m, off));

    __shared__ float smax[8];
    __shared__ float ssum[8];
    if (!lane) smax[warp] = m;
    __syncthreads();
    m = smax[0];
#pragma unroll
    for (int w = 1; w < 8; ++w) m = fmaxf(m, smax[w]);

    float s = 0.0f;
#pragma unroll
    for (int i = 0; i < 8; ++i) { x[i] = __expf(x[i] - m); s += x[i]; }
#pragma unroll
    for (int off = 16; off; off >>= 1) s += __shfl_xor_sync(0xffffffffu, s, off);
    if (!lane) ssum[warp] = s;
    __syncthreads();
    s = 0.0f;
#pragma unroll
    for (int w = 0; w < 8; ++w) s += ssum[w];

    const float inv = 1.0f / s;
#pragma unroll
    for (int i = 0; i < 8; ++i) row[t + 256 * i] = x[i] * inv;
}

// ---------------------------------------------------------------------------
// Kernel 4: attn_out = P @ V. grid = (1, S/128, BH). K = S = 2048.
// ---------------------------------------------------------------------------
__global__ __launch_bounds__(256, 2)
void pv_kernel() {
    const int z = blockIdx.z;
    const float* A = g_scores + (size_t)z * S_ * S_;
    const float* V = g_v + (size_t)z * S_ * HD_;

    __shared__ float As[16][128];
    __shared__ float Bs[16][128];

    const int tid = threadIdx.x;
    const int ty = tid >> 4, tx = tid & 15;
    const int m0 = blockIdx.y * 128;
    const int arow = tid >> 1, acol = (tid & 1) * 8;
    const int brow = tid >> 4, bcol = (tid & 15) * 8;

    float acc[8][8];
#pragma unroll
    for (int i = 0; i < 8; ++i)
#pragma unroll
        for (int j = 0; j < 8; ++j) acc[i][j] = 0.0f;

    const float* aptr = A + (size_t)(m0 + arow) * S_ + acol;
    const float* bptr = V + (size_t)brow * HD_ + bcol;

    float4 a0 = *(const float4*)(aptr);
    float4 a1 = *(const float4*)(aptr + 4);
    float4 b0 = *(const float4*)(bptr);
    float4 b1 = *(const float4*)(bptr + 4);

    for (int k0 = 0; k0 < S_; k0 += 16) {
        store_a_frag(As, acol, arow, a0, a1);
        store_b_frag(Bs, brow, bcol, b0, b1);
        __syncthreads();
        if (k0 + 16 < S_) {
            a0 = *(const float4*)(aptr + k0 + 16);
            a1 = *(const float4*)(aptr + k0 + 20);
            b0 = *(const float4*)(bptr + (size_t)(k0 + 16) * HD_);
            b1 = *(const float4*)(bptr + (size_t)(k0 + 16) * HD_ + 4);
        }
        mma_tile(As, Bs, ty, tx, acc);
        __syncthreads();
    }

    float* obase = g_attn + (size_t)z * S_ * HD_;
#pragma unroll
    for (int i = 0; i < 8; ++i) {
        int srow = m0 + ty * 8 + i;
        float* orow = obase + (size_t)srow * HD_;
#pragma unroll
        for (int j = 0; j < 8; ++j)
            orow[tx * 8 + j] = acc[i][j];
    }
}

// ---------------------------------------------------------------------------
// Kernel 5: out = gather(attn) @ W_O + b_O. grid = (H/128, M/128).
// A[m][k] gathered from g_attn [B, NH, S, HD].
// ---------------------------------------------------------------------------
__global__ __launch_bounds__(256, 2)
void out_kernel(const float* __restrict__ wo, const float* __restrict__ bo,
                float* __restrict__ out) {
    __shared__ float As[16][128];
    __shared__ float Bs[16][128];

    const int tid = threadIdx.x;
    const int ty = tid >> 4, tx = tid & 15;
    const int m0 = blockIdx.y * 128, n0 = blockIdx.x * 128;
    const int arow = tid >> 1, acol = (tid & 1) * 8;
    const int brow = tid >> 4, bcol = (tid & 15) * 8;

    float acc[8][8];
#pragma unroll
    for (int i = 0; i < 8; ++i)
#pragma unroll
        for (int j = 0; j < 8; ++j) acc[i][j] = 0.0f;

    const int m = m0 + arow;
    const int b = m >> 11, s = m & (S_ - 1);
    const float* bptr = wo + (size_t)brow * H_ + n0 + bcol;

    // gathered A address for column block k0: head = (k0+acol)>>7, d = (k0+acol)&127
    auto a_addr = [&](int k0) -> const float* {
        int kk = k0 + acol;
        int h = kk >> 7, d = kk & (HD_ - 1);
        return g_attn + ((size_t)(b * NH_ + h) * S_ + s) * HD_ + d;
    };

    const float* ap = a_addr(0);
    float4 a0 = *(const float4*)(ap);
    float4 a1 = *(const float4*)(ap + 4);
    float4 b0 = *(const float4*)(bptr);
    float4 b1 = *(const float4*)(bptr + 4);

    for (int k0 = 0; k0 < H_; k0 += 16) {
        store_a_frag(As, acol, arow, a0, a1);
        store_b_frag(Bs, brow, bcol, b0, b1);
        __syncthreads();
        if (k0 + 16 < H_) {
            const float* apn = a_addr(k0 + 16);
            a0 = *(const float4*)(apn);
            a1 = *(const float4*)(apn + 4);
            b0 = *(const float4*)(bptr + (size_t)(k0 + 16) * H_);
            b1 = *(const float4*)(bptr + (size_t)(k0 + 16) * H_ + 4);
        }
        mma_tile(As, Bs, ty, tx, acc);
        __syncthreads();
    }

#pragma unroll
    for (int i = 0; i < 8; ++i) {
        int mm = m0 + ty * 8 + i;
        float* orow = out + (size_t)mm * H_;
#pragma unroll
        for (int j = 0; j < 8; ++j) {
            int n = n0 + tx * 8 + j;
            orow[n] = acc[i][j] + bo[n];
        }
    }
}

// ---------------------------------------------------------------------------
// Launch
// ---------------------------------------------------------------------------
extern "C" void kernel_launch(void* const* d_in, const int* in_sizes, int n_in,
                              void* d_out, int out_size) {
    const float* batch = (const float*)d_in[0];
    const float* mask  = (const float*)d_in[1];
    const float* wq = (const float*)d_in[2]; const float* bq = (const float*)d_in[3];
    const float* wk = (const float*)d_in[4]; const float* bk = (const float*)d_in[5];
    const float* wv = (const float*)d_in[6]; const float* bv = (const float*)d_in[7];
    const float* wo = (const float*)d_in[8]; const float* bo = (const float*)d_in[9];
    float* out = (float*)d_out;

    dim3 blk(256);
    qkv_kernel<<<dim3(H_ / 128, M_ / 128, 3), blk>>>(batch, wq, bq, wk, bk, wv, bv);
    scores_kernel<<<dim3(S_ / 128, S_ / 128, BH_), blk>>>(mask);
    softmax_kernel<<<dim3(S_, BH_), blk>>>();
    pv_kernel<<<dim3(1, S_ / 128, BH_), blk>>>();
    out_kernel<<<dim3(H_ / 128, M_ / 128, 1), blk>>>(wo, bo, out);
}

// round 4
// speedup vs baseline: 1.0004x; 1.0004x over previous
#include <cuda_runtime.h>

// Problem constants
#define B_   2
#define S_   2048
#define H_   2048
#define NH_  16
#define HD_  128
#define M_   (B_ * S_)    // 4096 rows for the big GEMMs
#define BH_  (B_ * NH_)   // 32 (batch*heads)

// Scratch (device globals: allocation-free per harness rules)
__device__ float g_q[(size_t)BH_ * S_ * HD_];      //  32 MB
__device__ float g_k[(size_t)BH_ * S_ * HD_];      //  32 MB
__device__ float g_v[(size_t)BH_ * S_ * HD_];      //  32 MB
__device__ float g_attn[(size_t)BH_ * S_ * HD_];   //  32 MB
__device__ float g_scores[(size_t)BH_ * S_ * S_];  // 512 MB

// ---------------------------------------------------------------------------
// Shared GEMM micro-kernel pieces: 128x128 tile, BK=16, 256 threads,
// 8x8 per-thread accumulators.
// ---------------------------------------------------------------------------

__device__ __forceinline__ void store_a_frag(float As[16][128], int acol, int arow,
                                             float4 a0, float4 a1) {
    As[acol + 0][arow] = a0.x; As[acol + 1][arow] = a0.y;
    As[acol + 2][arow] = a0.z; As[acol + 3][arow] = a0.w;
    As[acol + 4][arow] = a1.x; As[acol + 5][arow] = a1.y;
    As[acol + 6][arow] = a1.z; As[acol + 7][arow] = a1.w;
}

__device__ __forceinline__ void store_b_frag(float Bs[16][128], int brow, int bcol,
                                             float4 b0, float4 b1) {
    *(float4*)&Bs[brow][bcol]     = b0;
    *(float4*)&Bs[brow][bcol + 4] = b1;
}

__device__ __forceinline__ void mma_tile(const float As[16][128], const float Bs[16][128],
                                         int ty, int tx, float acc[8][8]) {
#pragma unroll
    for (int kt = 0; kt < 16; ++kt) {
        float ar[8], br[8];
#pragma unroll
        for (int i = 0; i < 8; ++i) ar[i] = As[kt][ty * 8 + i];
#pragma unroll
        for (int j = 0; j < 8; ++j) br[j] = Bs[kt][tx * 8 + j];
#pragma unroll
        for (int i = 0; i < 8; ++i)
#pragma unroll
            for (int j = 0; j < 8; ++j)
                acc[i][j] += ar[i] * br[j];
    }
}

// ---------------------------------------------------------------------------
// Kernel 1: QKV projections. grid = (H/128, M/128, 3), z selects Q/K/V.
// Out layout: [B, NH, S, HD]  (head-major for attention).
// ---------------------------------------------------------------------------
__global__ __launch_bounds__(256, 2)
void qkv_kernel(const float* __restrict__ x,
                const float* __restrict__ wq, const float* __restrict__ bq,
                const float* __restrict__ wk, const float* __restrict__ bk,
                const float* __restrict__ wv, const float* __restrict__ bv) {
    const float* W; const float* bias; float* out;
    int z = blockIdx.z;
    if (z == 0)      { W = wq; bias = bq; out = g_q; }
    else if (z == 1) { W = wk; bias = bk; out = g_k; }
    else             { W = wv; bias = bv; out = g_v; }

    __shared__ float As[16][128];
    __shared__ float Bs[16][128];

    const int tid = threadIdx.x;
    const int ty = tid >> 4, tx = tid & 15;
    const int m0 = blockIdx.y * 128, n0 = blockIdx.x * 128;
    const int arow = tid >> 1, acol = (tid & 1) * 8;
    const int brow = tid >> 4, bcol = (tid & 15) * 8;

    float acc[8][8];
#pragma unroll
    for (int i = 0; i < 8; ++i)
#pragma unroll
        for (int j = 0; j < 8; ++j) acc[i][j] = 0.0f;

    const float* aptr = x + (size_t)(m0 + arow) * H_ + acol;
    const float* bptr = W + (size_t)brow * H_ + n0 + bcol;

    float4 a0 = *(const float4*)(aptr);
    float4 a1 = *(const float4*)(aptr + 4);
    float4 b0 = *(const float4*)(bptr);
    float4 b1 = *(const float4*)(bptr + 4);

    for (int k0 = 0; k0 < H_; k0 += 16) {
        store_a_frag(As, acol, arow, a0, a1);
        store_b_frag(Bs, brow, bcol, b0, b1);
        __syncthreads();
        if (k0 + 16 < H_) {
            a0 = *(const float4*)(aptr + k0 + 16);
            a1 = *(const float4*)(aptr + k0 + 20);
            b0 = *(const float4*)(bptr + (size_t)(k0 + 16) * H_);
            b1 = *(const float4*)(bptr + (size_t)(k0 + 16) * H_ + 4);
        }
        mma_tile(As, Bs, ty, tx, acc);
        __syncthreads();
    }

    const int h = blockIdx.x;  // H/128 == NH so block-col == head
#pragma unroll
    for (int i = 0; i < 8; ++i) {
        int m = m0 + ty * 8 + i;
        int b = m >> 11, s = m & (S_ - 1);
        float* orow = out + ((size_t)(b * NH_ + h) * S_ + s) * HD_;
#pragma unroll
        for (int j = 0; j < 8; ++j) {
            int d = tx * 8 + j;
            orow[d] = acc[i][j] + bias[h * HD_ + d];
        }
    }
}

// ---------------------------------------------------------------------------
// Kernel 2: scores = (Q @ K^T) * scale + mask. grid = (S/128, S/128, BH).
// ---------------------------------------------------------------------------
__global__ __launch_bounds__(256, 2)
void scores_kernel(const float* __restrict__ mask) {
    const int z = blockIdx.z;
    const float* Q = g_q + (size_t)z * S_ * HD_;
    const float* K = g_k + (size_t)z * S_ * HD_;

    __shared__ float As[16][128];
    __shared__ float Bs[16][128];

    const int tid = threadIdx.x;
    const int ty = tid >> 4, tx = tid & 15;
    const int q0 = blockIdx.y * 128, n0 = blockIdx.x * 128;
    const int arow = tid >> 1, acol = (tid & 1) * 8;  // A loader
    const int nrow = tid >> 1, kq   = (tid & 1) * 8;  // B loader (transposed)

    float acc[8][8];
#pragma unroll
    for (int i = 0; i < 8; ++i)
#pragma unroll
        for (int j = 0; j < 8; ++j) acc[i][j] = 0.0f;

    const float* aptr = Q + (size_t)(q0 + arow) * HD_ + acol;
    const float* bptr = K + (size_t)(n0 + nrow) * HD_ + kq;

    float4 a0 = *(const float4*)(aptr);
    float4 a1 = *(const float4*)(aptr + 4);
    float4 b0 = *(const float4*)(bptr);
    float4 b1 = *(const float4*)(bptr + 4);

    for (int k0 = 0; k0 < HD_; k0 += 16) {
        store_a_frag(As, acol, arow, a0, a1);
        store_a_frag(Bs, kq, nrow, b0, b1);  // transposed store: Bs[k][n]
        __syncthreads();
        if (k0 + 16 < HD_) {
            a0 = *(const float4*)(aptr + k0 + 16);
            a1 = *(const float4*)(aptr + k0 + 20);
            b0 = *(const float4*)(bptr + k0 + 16);
            b1 = *(const float4*)(bptr + k0 + 20);
        }
        mma_tile(As, Bs, ty, tx, acc);
        __syncthreads();
    }

    const float scale = 0.08838834764831845f;  // 1/sqrt(128)
    const int b = z >> 4;
    float* srow_base = g_scores + (size_t)z * S_ * S_;
#pragma unroll
    for (int i = 0; i < 8; ++i) {
        int q = q0 + ty * 8 + i;
        const float* mrow = mask + ((size_t)b * S_ + q) * S_;
        float* srow = srow_base + (size_t)q * S_;
#pragma unroll
        for (int j = 0; j < 8; ++j) {
            int kc = n0 + tx * 8 + j;
            srow[kc] = acc[i][j] * scale + mrow[kc];
        }
    }
}

// ---------------------------------------------------------------------------
// Kernel 3: row softmax over S=2048. grid = (S, BH), 256 threads, 8 elts/thread.
// ---------------------------------------------------------------------------
__global__ __launch_bounds__(256)
void softmax_kernel() {
    const int q = blockIdx.x, z = blockIdx.y;
    float* row = g_scores + ((size_t)z * S_ + q) * S_;
    const int t = threadIdx.x;
    const int warp = t >> 5, lane = t & 31;

    float x[8];
#pragma unroll
    for (int i = 0; i < 8; ++i) x[i] = row[t + 256 * i];

    float m = x[0];
#pragma unroll
    for (int i = 1; i < 8; ++i) m = fmaxf(m, x[i]);
#pragma unroll
    for (int off = 16; off; off >>= 1) m = fmaxf(m, __shfl_xor_sync(0xffffffffu, m, off));

    __shared__ float smax[8];
    __shared__ float ssum[8];
    if (!lane) smax[warp] = m;
    __syncthreads();
    m = smax[0];
#pragma unroll
    for (int w = 1; w < 8; ++w) m = fmaxf(m, smax[w]);

    float s = 0.0f;
#pragma unroll
    for (int i = 0; i < 8; ++i) { x[i] = __expf(x[i] - m); s += x[i]; }
#pragma unroll
    for (int off = 16; off; off >>= 1) s += __shfl_xor_sync(0xffffffffu, s, off);
    if (!lane) ssum[warp] = s;
    __syncthreads();
    s = 0.0f;
#pragma unroll
    for (int w = 0; w < 8; ++w) s += ssum[w];

    const float inv = 1.0f / s;
#pragma unroll
    for (int i = 0; i < 8; ++i) row[t + 256 * i] = x[i] * inv;
}

// ---------------------------------------------------------------------------
// Kernel 4: attn_out = P @ V. grid = (1, S/128, BH). K = S = 2048.
// ---------------------------------------------------------------------------
__global__ __launch_bounds__(256, 2)
void pv_kernel() {
    const int z = blockIdx.z;
    const float* A = g_scores + (size_t)z * S_ * S_;
    const float* V = g_v + (size_t)z * S_ * HD_;

    __shared__ float As[16][128];
    __shared__ float Bs[16][128];

    const int tid = threadIdx.x;
    const int ty = tid >> 4, tx = tid & 15;
    const int m0 = blockIdx.y * 128;
    const int arow = tid >> 1, acol = (tid & 1) * 8;
    const int brow = tid >> 4, bcol = (tid & 15) * 8;

    float acc[8][8];
#pragma unroll
    for (int i = 0; i < 8; ++i)
#pragma unroll
        for (int j = 0; j < 8; ++j) acc[i][j] = 0.0f;

    const float* aptr = A + (size_t)(m0 + arow) * S_ + acol;
    const float* bptr = V + (size_t)brow * HD_ + bcol;

    float4 a0 = *(const float4*)(aptr);
    float4 a1 = *(const float4*)(aptr + 4);
    float4 b0 = *(const float4*)(bptr);
    float4 b1 = *(const float4*)(bptr + 4);

    for (int k0 = 0; k0 < S_; k0 += 16) {
        store_a_frag(As, acol, arow, a0, a1);
        store_b_frag(Bs, brow, bcol, b0, b1);
        __syncthreads();
        if (k0 + 16 < S_) {
            a0 = *(const float4*)(aptr + k0 + 16);
            a1 = *(const float4*)(aptr + k0 + 20);
            b0 = *(const float4*)(bptr + (size_t)(k0 + 16) * HD_);
            b1 = *(const float4*)(bptr + (size_t)(k0 + 16) * HD_ + 4);
        }
        mma_tile(As, Bs, ty, tx, acc);
        __syncthreads();
    }

    float* obase = g_attn + (size_t)z * S_ * HD_;
#pragma unroll
    for (int i = 0; i < 8; ++i) {
        int srow = m0 + ty * 8 + i;
        float* orow = obase + (size_t)srow * HD_;
#pragma unroll
        for (int j = 0; j < 8; ++j)
            orow[tx * 8 + j] = acc[i][j];
    }
}

// ---------------------------------------------------------------------------
// Kernel 5: out = gather(attn) @ W_O + b_O. grid = (H/128, M/128).
// A[m][k] gathered from g_attn [B, NH, S, HD].
// ---------------------------------------------------------------------------
__global__ __launch_bounds__(256, 2)
void out_kernel(const float* __restrict__ wo, const float* __restrict__ bo,
                float* __restrict__ out) {
    __shared__ float As[16][128];
    __shared__ float Bs[16][128];

    const int tid = threadIdx.x;
    const int ty = tid >> 4, tx = tid & 15;
    const int m0 = blockIdx.y * 128, n0 = blockIdx.x * 128;
    const int arow = tid >> 1, acol = (tid & 1) * 8;
    const int brow = tid >> 4, bcol = (tid & 15) * 8;

    float acc[8][8];
#pragma unroll
    for (int i = 0; i < 8; ++i)
#pragma unroll
        for (int j = 0; j < 8; ++j) acc[i][j] = 0.0f;

    const int m = m0 + arow;
    const int b = m >> 11, s = m & (S_ - 1);
    const float* bptr = wo + (size_t)brow * H_ + n0 + bcol;

    // gathered A address for column block k0: head = (k0+acol)>>7, d = (k0+acol)&127
    auto a_addr = [&](int k0) -> const float* {
        int kk = k0 + acol;
        int h = kk >> 7, d = kk & (HD_ - 1);
        return g_attn + ((size_t)(b * NH_ + h) * S_ + s) * HD_ + d;
    };

    const float* ap = a_addr(0);
    float4 a0 = *(const float4*)(ap);
    float4 a1 = *(const float4*)(ap + 4);
    float4 b0 = *(const float4*)(bptr);
    float4 b1 = *(const float4*)(bptr + 4);

    for (int k0 = 0; k0 < H_; k0 += 16) {
        store_a_frag(As, acol, arow, a0, a1);
        store_b_frag(Bs, brow, bcol, b0, b1);
        __syncthreads();
        if (k0 + 16 < H_) {
            const float* apn = a_addr(k0 + 16);
            a0 = *(const float4*)(apn);
            a1 = *(const float4*)(apn + 4);
            b0 = *(const float4*)(bptr + (size_t)(k0 + 16) * H_);
            b1 = *(const float4*)(bptr + (size_t)(k0 + 16) * H_ + 4);
        }
        mma_tile(As, Bs, ty, tx, acc);
        __syncthreads();
    }

#pragma unroll
    for (int i = 0; i < 8; ++i) {
        int mm = m0 + ty * 8 + i;
        float* orow = out + (size_t)mm * H_;
#pragma unroll
        for (int j = 0; j < 8; ++j) {
            int n = n0 + tx * 8 + j;
            orow[n] = acc[i][j] + bo[n];
        }
    }
}

// ---------------------------------------------------------------------------
// Launch
// ---------------------------------------------------------------------------
extern "C" void kernel_launch(void* const* d_in, const int* in_sizes, int n_in,
                              void* d_out, int out_size) {
    const float* batch = (const float*)d_in[0];
    const float* mask  = (const float*)d_in[1];
    const float* wq = (const float*)d_in[2]; const float* bq = (const float*)d_in[3];
    const float* wk = (const float*)d_in[4]; const float* bk = (const float*)d_in[5];
    const float* wv = (const float*)d_in[6]; const float* bv = (const float*)d_in[7];
    const float* wo = (const float*)d_in[8]; const float* bo = (const float*)d_in[9];
    float* out = (float*)d_out;

    dim3 blk(256);
    qkv_kernel<<<dim3(H_ / 128, M_ / 128, 3), blk>>>(batch, wq, bq, wk, bk, wv, bv);
    scores_kernel<<<dim3(S_ / 128, S_ / 128, BH_), blk>>>(mask);
    softmax_kernel<<<dim3(S_, BH_), blk>>>();
    pv_kernel<<<dim3(1, S_ / 128, BH_), blk>>>();
    out_kernel<<<dim3(H_ / 128, M_ / 128, 1), blk>>>(wo, bo, out);
}

// round 7
// speedup vs baseline: 2.3505x; 2.3497x over previous
#include <cuda_runtime.h>
#include <cuda_bf16.h>
#include <cstdint>

#define B_   2
#define S_   2048
#define H_   2048
#define NH_  16
#define HD_  128
#define M_   (B_ * S_)
#define BH_  (B_ * NH_)

// Scratch (device globals; allocation-free per harness rules)
__device__ float g_wt[4][(size_t)H_ * H_];          // 64 MB  transposed weights WT[n][k] = W[k][n]
__device__ float g_q[(size_t)BH_ * S_ * HD_];       // 32 MB  [b,h,s,d]
__device__ float g_k[(size_t)BH_ * S_ * HD_];       // 32 MB  [b,h,s,d]
__device__ float g_vT[(size_t)BH_ * HD_ * S_];      // 32 MB  [b,h,d,s]
__device__ float g_attn[(size_t)BH_ * S_ * HD_];    // 32 MB  [b,h,s,d]
__device__ float g_scores[(size_t)BH_ * S_ * S_];   // 512 MB

// ---------------------------------------------------------------------------
// SMEM geometry: per stage 4 bf16 tiles of 128 rows x 32 k, padded row stride
// 40 halves (80 B) -> 16B-aligned ldmatrix rows, conflict-free (80*r mod 128
// hits all eight 16B banks-groups). Tile = 10240 B.
//   stage base = s*40960:  Ahi +0 | Alo +10240 | Bhi +20480 | Blo +30720
// ---------------------------------------------------------------------------
static constexpr int TILE_B  = 10240;
static constexpr int STAGE_B = 4 * TILE_B;          // 40960
static constexpr int SMEM_BYTES = 2 * STAGE_B;      // 81920

__device__ __forceinline__ uint32_t smem_u32(const void* p) {
    uint32_t a;
    asm("{ .reg .u64 t; cvta.to.shared.u64 t, %1; cvt.u32.u64 %0, t; }" : "=r"(a) : "l"(p));
    return a;
}

__device__ __forceinline__ void ldm4(uint32_t* r, uint32_t addr) {
    asm volatile("ldmatrix.sync.aligned.m8n8.x4.shared.b16 {%0,%1,%2,%3}, [%4];"
        : "=r"(r[0]), "=r"(r[1]), "=r"(r[2]), "=r"(r[3]) : "r"(addr));
}

__device__ __forceinline__ void mma_bf16(float* c, const uint32_t* a, const uint32_t* b) {
    asm volatile(
        "mma.sync.aligned.m16n8k16.row.col.f32.bf16.bf16.f32 "
        "{%0,%1,%2,%3}, {%4,%5,%6,%7}, {%8,%9}, {%0,%1,%2,%3};"
        : "+f"(c[0]), "+f"(c[1]), "+f"(c[2]), "+f"(c[3])
        : "r"(a[0]), "r"(a[1]), "r"(a[2]), "r"(a[3]), "r"(b[0]), "r"(b[1]));
}

// Split fp32 -> bf16 hi + bf16 lo and store 8B each.
__device__ __forceinline__ void cvt_store(char* hip, char* lop, float4 v) {
    __nv_bfloat162 h0 = __floats2bfloat162_rn(v.x, v.y);
    __nv_bfloat162 h1 = __floats2bfloat162_rn(v.z, v.w);
    float lx = v.x - __bfloat162float(h0.x);
    float ly = v.y - __bfloat162float(h0.y);
    float lz = v.z - __bfloat162float(h1.x);
    float lw = v.w - __bfloat162float(h1.y);
    __nv_bfloat162 l0 = __floats2bfloat162_rn(lx, ly);
    __nv_bfloat162 l1 = __floats2bfloat162_rn(lz, lw);
    uint2 hu; hu.x = *reinterpret_cast<uint32_t*>(&h0); hu.y = *reinterpret_cast<uint32_t*>(&h1);
    uint2 lu; lu.x = *reinterpret_cast<uint32_t*>(&l0); lu.y = *reinterpret_cast<uint32_t*>(&l1);
    *reinterpret_cast<uint2*>(hip) = hu;
    *reinterpret_cast<uint2*>(lop) = lu;
}

// Prefetch one 128x32 fp32 tile pair into regs (4 float4 each per thread).
__device__ __forceinline__ void load_regs(const float* __restrict__ ap, size_t lda,
                                          const float* __restrict__ bp, size_t ldb,
                                          int tid, float4* pa, float4* pb) {
#pragma unroll
    for (int i = 0; i < 4; ++i) {
        int idx = tid + (i << 8), r = idx >> 3, c = idx & 7;
        pa[i] = *(const float4*)(ap + (size_t)r * lda + (c << 2));
        pb[i] = *(const float4*)(bp + (size_t)r * ldb + (c << 2));
    }
}

__device__ __forceinline__ void store_stage(char* smem, int s, int tid,
                                            const float4* pa, const float4* pb) {
    char* base = smem + s * STAGE_B;
#pragma unroll
    for (int i = 0; i < 4; ++i) {
        int idx = tid + (i << 8), r = idx >> 3, c = idx & 7;
        uint32_t off = (uint32_t)(r * 80 + c * 8);
        cvt_store(base + off,             base + TILE_B + off,     pa[i]);
        cvt_store(base + 2 * TILE_B + off, base + 3 * TILE_B + off, pb[i]);
    }
}

// One BK=32 stage of split-bf16 MMAs (2 x k16). acc[i][j][4] = 64x32 warp tile.
__device__ __forceinline__ void compute_stage(uint32_t stage_base, uint32_t aoff, uint32_t boff,
                                              float acc[4][4][4]) {
#pragma unroll
    for (int kk = 0; kk < 2; ++kk) {
        uint32_t ah[4][4], al[4][4], bh[4][2], bl[4][2];
        uint32_t ab = stage_base + aoff + kk * 32u;
        uint32_t bb = stage_base + 2u * TILE_B + boff + kk * 32u;
#pragma unroll
        for (int i = 0; i < 4; ++i) {
            ldm4(ah[i], ab + (uint32_t)i * 1280u);
            ldm4(al[i], ab + (uint32_t)TILE_B + (uint32_t)i * 1280u);
        }
#pragma unroll
        for (int s2 = 0; s2 < 2; ++s2) {
            uint32_t t[4];
            ldm4(t, bb + (uint32_t)s2 * 1280u);
            bh[s2 * 2][0] = t[0]; bh[s2 * 2][1] = t[1];
            bh[s2 * 2 + 1][0] = t[2]; bh[s2 * 2 + 1][1] = t[3];
            ldm4(t, bb + (uint32_t)TILE_B + (uint32_t)s2 * 1280u);
            bl[s2 * 2][0] = t[0]; bl[s2 * 2][1] = t[1];
            bl[s2 * 2 + 1][0] = t[2]; bl[s2 * 2 + 1][1] = t[3];
        }
#pragma unroll
        for (int i = 0; i < 4; ++i)
#pragma unroll
            for (int j = 0; j < 4; ++j) {
                mma_bf16(acc[i][j], ah[i], bh[j]);
                mma_bf16(acc[i][j], ah[i], bl[j]);
                mma_bf16(acc[i][j], al[i], bh[j]);
            }
    }
}

// Full GEMM driver. af(it)/bf(it) give fp32 tile base pointers for k0=it*32.
template <int NIT, typename AF, typename BF>
__device__ __forceinline__ void gemm_run(char* smem, int tid, AF af, size_t lda,
                                         BF bf, size_t ldb, float acc[4][4][4]) {
    const int lane = tid & 31, wid = tid >> 5;
    const int wm = (wid >> 2) * 64, wn = (wid & 3) * 32;
    const uint32_t aoff = (uint32_t)((wm + (lane & 7) + ((lane >> 3) & 1) * 8) * 80
                                     + ((lane >> 4) * 8) * 2);
    const uint32_t boff = (uint32_t)((wn + (lane & 7) + (lane >> 4) * 8) * 80
                                     + (((lane >> 3) & 1) * 8) * 2);
    const uint32_t sbase = smem_u32(smem);

#pragma unroll
    for (int i = 0; i < 4; ++i)
#pragma unroll
        for (int j = 0; j < 4; ++j)
#pragma unroll
            for (int e = 0; e < 4; ++e) acc[i][j][e] = 0.0f;

    {
        float4 pa[4], pb[4];
        load_regs(af(0), lda, bf(0), ldb, tid, pa, pb);
        store_stage(smem, 0, tid, pa, pb);
    }
    __syncthreads();

    for (int it = 0; it < NIT; ++it) {
        int cur = it & 1;
        float4 pa[4], pb[4];
        if (it + 1 < NIT) load_regs(af(it + 1), lda, bf(it + 1), ldb, tid, pa, pb);
        compute_stage(sbase + (uint32_t)cur * STAGE_B, aoff, boff, acc);
        if (it + 1 < NIT) store_stage(smem, cur ^ 1, tid, pa, pb);
        __syncthreads();
    }
}

// Epilogue index helpers: element (i,j,half,e) sits at
//   m = wm + i*16 + (lane>>2) + half*8 ,  n = wn + j*8 + (lane&3)*2 + e
// ---------------------------------------------------------------------------
// Weight transpose: g_wt[z][n][k] = W_z[k][n]
// ---------------------------------------------------------------------------
__global__ __launch_bounds__(256)
void transpose_w(const float* __restrict__ wq, const float* __restrict__ wk,
                 const float* __restrict__ wv, const float* __restrict__ wo) {
    int z = blockIdx.z;
    const float* src = (z == 0) ? wq : (z == 1) ? wk : (z == 2) ? wv : wo;
    float* dst = g_wt[z];
    __shared__ float t[32][33];
    int x0 = blockIdx.x * 32, y0 = blockIdx.y * 32;
    int tx = threadIdx.x, ty = threadIdx.y;
#pragma unroll
    for (int j = 0; j < 32; j += 8)
        t[ty + j][tx] = src[(size_t)(y0 + ty + j) * H_ + x0 + tx];
    __syncthreads();
#pragma unroll
    for (int j = 0; j < 32; j += 8)
        dst[(size_t)(x0 + ty + j) * H_ + y0 + tx] = t[tx][ty + j];
}

// ---------------------------------------------------------------------------
// Kernel 1: QKV projections. grid (16, 32, 3). Q,K -> [b,h,s,d]; V -> [b,h,d,s].
// ---------------------------------------------------------------------------
__global__ __launch_bounds__(256)
void qkv_mma(const float* __restrict__ x, const float* __restrict__ bq,
             const float* __restrict__ bk, const float* __restrict__ bv) {
    extern __shared__ char smem[];
    const int tid = threadIdx.x, lane = tid & 31, wid = tid >> 5;
    const int wm = (wid >> 2) * 64, wn = (wid & 3) * 32;
    const int z = blockIdx.z, h = blockIdx.x, m0 = blockIdx.y * 128, n0 = h * 128;
    const float* wt = g_wt[z];
    const float* bias = (z == 0) ? bq : (z == 1) ? bk : bv;

    float acc[4][4][4];
    gemm_run<64>(smem, tid,
                 [&](int it) { return x + (size_t)m0 * H_ + it * 32; }, (size_t)H_,
                 [&](int it) { return wt + (size_t)n0 * H_ + it * 32; }, (size_t)H_, acc);

    const int bb = m0 >> 11, s0 = m0 & (S_ - 1);
    if (z < 2) {
        float* base = ((z == 0) ? g_q : g_k) + (size_t)(bb * NH_ + h) * S_ * HD_;
#pragma unroll
        for (int i = 0; i < 4; ++i)
#pragma unroll
            for (int j = 0; j < 4; ++j)
#pragma unroll
                for (int hf = 0; hf < 2; ++hf) {
                    int s = s0 + wm + i * 16 + (lane >> 2) + hf * 8;
                    int d = wn + j * 8 + ((lane & 3) << 1);
                    float2 v = make_float2(acc[i][j][hf * 2] + bias[n0 + d],
                                           acc[i][j][hf * 2 + 1] + bias[n0 + d + 1]);
                    *(float2*)(base + (size_t)s * HD_ + d) = v;
                }
    } else {
        float* vb = g_vT + (size_t)(bb * NH_ + h) * HD_ * S_;
#pragma unroll
        for (int i = 0; i < 4; ++i)
#pragma unroll
            for (int j = 0; j < 4; ++j)
#pragma unroll
                for (int hf = 0; hf < 2; ++hf) {
                    int s = s0 + wm + i * 16 + (lane >> 2) + hf * 8;
                    int d = wn + j * 8 + ((lane & 3) << 1);
                    vb[(size_t)d * S_ + s]       = acc[i][j][hf * 2] + bias[n0 + d];
                    vb[(size_t)(d + 1) * S_ + s] = acc[i][j][hf * 2 + 1] + bias[n0 + d + 1];
                }
    }
}

// ---------------------------------------------------------------------------
// Kernel 2: scores = Q K^T * scale + mask.  grid (16, 16, 32)
// ---------------------------------------------------------------------------
__global__ __launch_bounds__(256)
void scores_mma(const float* __restrict__ mask) {
    extern __shared__ char smem[];
    const int tid = threadIdx.x, lane = tid & 31, wid = tid >> 5;
    const int wm = (wid >> 2) * 64, wn = (wid & 3) * 32;
    const int z = blockIdx.z, q0 = blockIdx.y * 128, n0 = blockIdx.x * 128;
    const float* Q = g_q + (size_t)z * S_ * HD_;
    const float* Kp = g_k + (size_t)z * S_ * HD_;

    float acc[4][4][4];
    gemm_run<4>(smem, tid,
                [&](int it) { return Q + (size_t)q0 * HD_ + it * 32; }, (size_t)HD_,
                [&](int it) { return Kp + (size_t)n0 * HD_ + it * 32; }, (size_t)HD_, acc);

    const float scale = 0.08838834764831845f;  // 1/sqrt(128)
    const int bb = z >> 4;
    float* sbase_ = g_scores + (size_t)z * S_ * S_;
#pragma unroll
    for (int i = 0; i < 4; ++i)
#pragma unroll
        for (int j = 0; j < 4; ++j)
#pragma unroll
            for (int hf = 0; hf < 2; ++hf) {
                int q = q0 + wm + i * 16 + (lane >> 2) + hf * 8;
                int kc = n0 + wn + j * 8 + ((lane & 3) << 1);
                float2 mk = *(const float2*)(mask + ((size_t)bb * S_ + q) * S_ + kc);
                float2 v = make_float2(acc[i][j][hf * 2] * scale + mk.x,
                                       acc[i][j][hf * 2 + 1] * scale + mk.y);
                *(float2*)(sbase_ + (size_t)q * S_ + kc) = v;
            }
}

// ---------------------------------------------------------------------------
// Kernel 3: row softmax over S=2048. grid (S, BH), 256 threads
// ---------------------------------------------------------------------------
__global__ __launch_bounds__(256)
void softmax_kernel() {
    const int q = blockIdx.x, z = blockIdx.y;
    float* row = g_scores + ((size_t)z * S_ + q) * S_;
    const int t = threadIdx.x;
    const int warp = t >> 5, lane = t & 31;

    float x[8];
#pragma unroll
    for (int i = 0; i < 8; ++i) x[i] = row[t + 256 * i];

    float m = x[0];
#pragma unroll
    for (int i = 1; i < 8; ++i) m = fmaxf(m, x[i]);
#pragma unroll
    for (int off = 16; off; off >>= 1) m = fmaxf(m, __shfl_xor_sync(0xffffffffu, m, off));

    __shared__ float smax[8];
    __shared__ float ssum[8];
    if (!lane) smax[warp] = m;
    __syncthreads();
    m = smax[0];
#pragma unroll
    for (int w = 1; w < 8; ++w) m = fmaxf(m, smax[w]);

    float s = 0.0f;
#pragma unroll
    for (int i = 0; i < 8; ++i) { x[i] = __expf(x[i] - m); s += x[i]; }
#pragma unroll
    for (int off = 16; off; off >>= 1) s += __shfl_xor_sync(0xffffffffu, s, off);
    if (!lane) ssum[warp] = s;
    __syncthreads();
    s = 0.0f;
#pragma unroll
    for (int w = 0; w < 8; ++w) s += ssum[w];

    const float inv = 1.0f / s;
#pragma unroll
    for (int i = 0; i < 8; ++i) row[t + 256 * i] = x[i] * inv;
}

// ---------------------------------------------------------------------------
// Kernel 4: attn = P @ V (via V^T).  grid (16, 32): x=q-block, y=z
// ---------------------------------------------------------------------------
__global__ __launch_bounds__(256)
void pv_mma() {
    extern __shared__ char smem[];
    const int tid = threadIdx.x, lane = tid & 31, wid = tid >> 5;
    const int wm = (wid >> 2) * 64, wn = (wid & 3) * 32;
    const int q0 = blockIdx.x * 128, z = blockIdx.y;
    const float* P = g_scores + (size_t)z * S_ * S_;
    const float* VT = g_vT + (size_t)z * HD_ * S_;

    float acc[4][4][4];
    gemm_run<64>(smem, tid,
                 [&](int it) { return P + (size_t)q0 * S_ + it * 32; }, (size_t)S_,
                 [&](int it) { return VT + it * 32; }, (size_t)S_, acc);

    float* obase = g_attn + (size_t)z * S_ * HD_;
#pragma unroll
    for (int i = 0; i < 4; ++i)
#pragma unroll
        for (int j = 0; j < 4; ++j)
#pragma unroll
            for (int hf = 0; hf < 2; ++hf) {
                int s = q0 + wm + i * 16 + (lane >> 2) + hf * 8;
                int d = wn + j * 8 + ((lane & 3) << 1);
                float2 v = make_float2(acc[i][j][hf * 2], acc[i][j][hf * 2 + 1]);
                *(float2*)(obase + (size_t)s * HD_ + d) = v;
            }
}

// ---------------------------------------------------------------------------
// Kernel 5: out = gather(attn) @ W_O + b_O.  grid (16, 32)
// ---------------------------------------------------------------------------
__global__ __launch_bounds__(256)
void out_mma(const float* __restrict__ bo, float* __restrict__ out) {
    extern __shared__ char smem[];
    const int tid = threadIdx.x, lane = tid & 31, wid = tid >> 5;
    const int wm = (wid >> 2) * 64, wn = (wid & 3) * 32;
    const int n0 = blockIdx.x * 128, m0 = blockIdx.y * 128;
    const int bb = m0 >> 11, s0 = m0 & (S_ - 1);
    const float* wt = g_wt[3];

    float acc[4][4][4];
    gemm_run<64>(smem, tid,
                 [&](int it) {
                     int h = it >> 2, dbase = (it & 3) * 32;
                     return g_attn + ((size_t)(bb * NH_ + h) * S_ + s0) * HD_ + dbase;
                 }, (size_t)HD_,
                 [&](int it) { return wt + (size_t)n0 * H_ + it * 32; }, (size_t)H_, acc);

#pragma unroll
    for (int i = 0; i < 4; ++i)
#pragma unroll
        for (int j = 0; j < 4; ++j)
#pragma unroll
            for (int hf = 0; hf < 2; ++hf) {
                int m = m0 + wm + i * 16 + (lane >> 2) + hf * 8;
                int n = n0 + wn + j * 8 + ((lane & 3) << 1);
                float2 v = make_float2(acc[i][j][hf * 2] + bo[n],
                                       acc[i][j][hf * 2 + 1] + bo[n + 1]);
                *(float2*)(out + (size_t)m * H_ + n) = v;
            }
}

// ---------------------------------------------------------------------------
// Launch
// ---------------------------------------------------------------------------
extern "C" void kernel_launch(void* const* d_in, const int* in_sizes, int n_in,
                              void* d_out, int out_size) {
    const float* batch = (const float*)d_in[0];
    const float* mask  = (const float*)d_in[1];
    const float* wq = (const float*)d_in[2]; const float* bq = (const float*)d_in[3];
    const float* wk = (const float*)d_in[4]; const float* bk = (const float*)d_in[5];
    const float* wv = (const float*)d_in[6]; const float* bv = (const float*)d_in[7];
    const float* wo = (const float*)d_in[8]; const float* bo = (const float*)d_in[9];
    float* out = (float*)d_out;

    cudaFuncSetAttribute(qkv_mma,    cudaFuncAttributeMaxDynamicSharedMemorySize, SMEM_BYTES);
    cudaFuncSetAttribute(scores_mma, cudaFuncAttributeMaxDynamicSharedMemorySize, SMEM_BYTES);
    cudaFuncSetAttribute(pv_mma,     cudaFuncAttributeMaxDynamicSharedMemorySize, SMEM_BYTES);
    cudaFuncSetAttribute(out_mma,    cudaFuncAttributeMaxDynamicSharedMemorySize, SMEM_BYTES);

    transpose_w<<<dim3(64, 64, 4), dim3(32, 8)>>>(wq, wk, wv, wo);
    qkv_mma<<<dim3(16, 32, 3), 256, SMEM_BYTES>>>(batch, bq, bk, bv);
    scores_mma<<<dim3(16, 16, 32), 256, SMEM_BYTES>>>(mask);
    softmax_kernel<<<dim3(S_, BH_), 256>>>();
    pv_mma<<<dim3(16, 32), 256, SMEM_BYTES>>>();
    out_mma<<<dim3(16, 32), 256, SMEM_BYTES>>>(bo, out);
}

// round 8
// speedup vs baseline: 2.9968x; 1.2750x over previous
#include <cuda_runtime.h>
#include <cuda_bf16.h>
#include <cstdint>

#define B_   2
#define S_   2048
#define H_   2048
#define NH_  16
#define HD_  128
#define M_   (B_ * S_)
#define BH_  (B_ * NH_)

// ---------------------------------------------------------------------------
// Device-global scratch (hi plane at [0], lo plane at [1])
// ---------------------------------------------------------------------------
__device__ __nv_bfloat16 g_wt2[4][2][(size_t)H_ * H_];     // 64 MB  WT[n][k], split
__device__ __nv_bfloat16 g_x2[2][(size_t)M_ * H_];         // 32 MB  batch, split
__device__ __nv_bfloat16 g_q2[2][(size_t)BH_ * S_ * HD_];  // 33 MB  [b,h,s,d]
__device__ __nv_bfloat16 g_k2[2][(size_t)BH_ * S_ * HD_];  // 33 MB  [b,h,s,d]
__device__ __nv_bfloat16 g_vT2[2][(size_t)BH_ * HD_ * S_]; // 33 MB  [b,h,d,s]
__device__ __nv_bfloat16 g_at2[2][(size_t)BH_ * S_ * HD_]; // 33 MB  [b,h,s,d]

static constexpr size_t LO_QKVA = (size_t)BH_ * S_ * HD_;  // plane stride (elems)

// ---------------------------------------------------------------------------
// PTX helpers
// ---------------------------------------------------------------------------
__device__ __forceinline__ uint32_t smem_u32(const void* p) {
    uint32_t a;
    asm("{ .reg .u64 t; cvta.to.shared.u64 t, %1; cvt.u32.u64 %0, t; }" : "=r"(a) : "l"(p));
    return a;
}

__device__ __forceinline__ void ldm4(uint32_t* r, uint32_t addr) {
    asm volatile("ldmatrix.sync.aligned.m8n8.x4.shared.b16 {%0,%1,%2,%3}, [%4];"
        : "=r"(r[0]), "=r"(r[1]), "=r"(r[2]), "=r"(r[3]) : "r"(addr));
}

__device__ __forceinline__ void mma_bf16(float* c, const uint32_t* a, const uint32_t* b) {
    asm volatile(
        "mma.sync.aligned.m16n8k16.row.col.f32.bf16.bf16.f32 "
        "{%0,%1,%2,%3}, {%4,%5,%6,%7}, {%8,%9}, {%0,%1,%2,%3};"
        : "+f"(c[0]), "+f"(c[1]), "+f"(c[2]), "+f"(c[3])
        : "r"(a[0]), "r"(a[1]), "r"(a[2]), "r"(a[3]), "r"(b[0]), "r"(b[1]));
}

#define CP16(dst, src)  asm volatile("cp.async.cg.shared.global [%0], [%1], 16;" :: "r"(dst), "l"(src))
#define CP_COMMIT()     asm volatile("cp.async.commit_group;" ::: "memory")
#define CP_WAIT0()      asm volatile("cp.async.wait_group 0;" ::: "memory")

// fp32 -> bf16 hi + bf16 lo (packed pair)
__device__ __forceinline__ void split2(float a, float b, uint32_t& hi, uint32_t& lo) {
    __nv_bfloat162 h = __floats2bfloat162_rn(a, b);
    __nv_bfloat162 l = __floats2bfloat162_rn(a - __bfloat162float(h.x), b - __bfloat162float(h.y));
    hi = *reinterpret_cast<uint32_t*>(&h);
    lo = *reinterpret_cast<uint32_t*>(&l);
}
__device__ __forceinline__ void split1(float v, __nv_bfloat16& h, __nv_bfloat16& l) {
    h = __float2bfloat16_rn(v);
    l = __float2bfloat16_rn(v - __bfloat162float(h));
}

// ---------------------------------------------------------------------------
// GEMM core (qkv/out): 128x128 tile, BK=32 bf16 hi/lo, cp.async double buffer
// Stage: Ahi +0 | Alo +10240 | Bhi +20480 | Blo +30720 ; row stride 80 B
// ---------------------------------------------------------------------------
static constexpr int TILE_B  = 10240;
static constexpr int STAGE_B = 4 * TILE_B;
static constexpr int SMEM_G  = 2 * STAGE_B;   // 81920

__device__ __forceinline__ void cpa_ab(uint32_t sb, int stage,
                                       const __nv_bfloat16* asrc, size_t lda, size_t aLO,
                                       const __nv_bfloat16* bsrc, size_t ldb, size_t bLO, int tid) {
    uint32_t base = sb + (uint32_t)stage * STAGE_B;
#pragma unroll
    for (int i = 0; i < 2; ++i) {
        int idx = tid + (i << 8), r = idx >> 2, c = idx & 3;
        const __nv_bfloat16* as = asrc + (size_t)r * lda + c * 8;
        uint32_t ad = base + (uint32_t)(r * 80 + c * 16);
        CP16(ad, as); CP16(ad + TILE_B, as + aLO);
        const __nv_bfloat16* bs = bsrc + (size_t)r * ldb + c * 8;
        uint32_t bd = base + 2u * TILE_B + (uint32_t)(r * 80 + c * 16);
        CP16(bd, bs); CP16(bd + TILE_B, bs + bLO);
    }
}

// One BK=32 stage of split-bf16 MMAs. acc = 64x32 warp tile.
__device__ __forceinline__ void compute_stage(uint32_t stage_base, uint32_t aoff, uint32_t boff,
                                              float acc[4][4][4]) {
#pragma unroll
    for (int kk = 0; kk < 2; ++kk) {
        uint32_t ah[4][4], al[4][4], bh[4][2], bl[4][2];
        uint32_t ab = stage_base + aoff + kk * 32u;
        uint32_t bb = stage_base + 2u * TILE_B + boff + kk * 32u;
#pragma unroll
        for (int i = 0; i < 4; ++i) {
            ldm4(ah[i], ab + (uint32_t)i * 1280u);
            ldm4(al[i], ab + (uint32_t)TILE_B + (uint32_t)i * 1280u);
        }
#pragma unroll
        for (int s2 = 0; s2 < 2; ++s2) {
            uint32_t t[4];
            ldm4(t, bb + (uint32_t)s2 * 1280u);
            bh[s2 * 2][0] = t[0]; bh[s2 * 2][1] = t[1];
            bh[s2 * 2 + 1][0] = t[2]; bh[s2 * 2 + 1][1] = t[3];
            ldm4(t, bb + (uint32_t)TILE_B + (uint32_t)s2 * 1280u);
            bl[s2 * 2][0] = t[0]; bl[s2 * 2][1] = t[1];
            bl[s2 * 2 + 1][0] = t[2]; bl[s2 * 2 + 1][1] = t[3];
        }
#pragma unroll
        for (int i = 0; i < 4; ++i)
#pragma unroll
            for (int j = 0; j < 4; ++j) {
                mma_bf16(acc[i][j], ah[i], bh[j]);
                mma_bf16(acc[i][j], ah[i], bl[j]);
                mma_bf16(acc[i][j], al[i], bh[j]);
            }
    }
}

template <int NIT, typename AF, typename BF>
__device__ __forceinline__ void gemm_run2(char* smem, int tid, AF af, size_t lda, size_t aLO,
                                          BF bf, size_t ldb, size_t bLO, float acc[4][4][4]) {
    const int lane = tid & 31, wid = tid >> 5;
    const int wm = (wid >> 2) * 64, wn = (wid & 3) * 32;
    const uint32_t aoff = (uint32_t)((wm + (lane & 7) + ((lane >> 3) & 1) * 8) * 80 + (lane >> 4) * 16);
    const uint32_t boff = (uint32_t)((wn + (lane & 7) + (lane >> 4) * 8) * 80 + ((lane >> 3) & 1) * 16);
    const uint32_t sb = smem_u32(smem);

#pragma unroll
    for (int i = 0; i < 4; ++i)
#pragma unroll
        for (int j = 0; j < 4; ++j)
#pragma unroll
            for (int e = 0; e < 4; ++e) acc[i][j][e] = 0.0f;

    cpa_ab(sb, 0, af(0), lda, aLO, bf(0), ldb, bLO, tid);
    CP_COMMIT(); CP_WAIT0(); __syncthreads();

    for (int it = 0; it < NIT; ++it) {
        int cur = it & 1;
        if (it + 1 < NIT) {
            cpa_ab(sb, cur ^ 1, af(it + 1), lda, aLO, bf(it + 1), ldb, bLO, tid);
            CP_COMMIT();
        }
        compute_stage(sb + (uint32_t)cur * STAGE_B, aoff, boff, acc);
        CP_WAIT0(); __syncthreads();
    }
}

// ---------------------------------------------------------------------------
// Prep: x -> bf16 hi/lo
// ---------------------------------------------------------------------------
__global__ __launch_bounds__(256)
void prep_x(const float* __restrict__ x) {
    size_t i = ((size_t)blockIdx.x * 256 + threadIdx.x) * 4;
    float4 v = *(const float4*)(x + i);
    uint32_t h0, l0, h1, l1;
    split2(v.x, v.y, h0, l0);
    split2(v.z, v.w, h1, l1);
    *(uint32_t*)(&g_x2[0][i])     = h0; *(uint32_t*)(&g_x2[0][i + 2]) = h1;
    *(uint32_t*)(&g_x2[1][i])     = l0; *(uint32_t*)(&g_x2[1][i + 2]) = l1;
}

// ---------------------------------------------------------------------------
// Weight transpose + split: g_wt2[z][.][n][k] = split(W_z[k][n])
// ---------------------------------------------------------------------------
__global__ __launch_bounds__(256)
void transpose_w(const float* __restrict__ wq, const float* __restrict__ wk,
                 const float* __restrict__ wv, const float* __restrict__ wo) {
    int z = blockIdx.z;
    const float* src = (z == 0) ? wq : (z == 1) ? wk : (z == 2) ? wv : wo;
    __shared__ float t[32][33];
    int x0 = blockIdx.x * 32, y0 = blockIdx.y * 32;
    int tx = threadIdx.x, ty = threadIdx.y;
#pragma unroll
    for (int j = 0; j < 32; j += 8)
        t[ty + j][tx] = src[(size_t)(y0 + ty + j) * H_ + x0 + tx];
    __syncthreads();
#pragma unroll
    for (int j = 0; j < 32; j += 8) {
        __nv_bfloat16 h, l;
        split1(t[tx][ty + j], h, l);
        size_t o = (size_t)(x0 + ty + j) * H_ + y0 + tx;
        g_wt2[z][0][o] = h;
        g_wt2[z][1][o] = l;
    }
}

// ---------------------------------------------------------------------------
// Kernel 1: QKV projections. grid (16, 32, 3). Q,K -> hi/lo [b,h,s,d]; V -> hi/lo [b,h,d,s].
// ---------------------------------------------------------------------------
__global__ __launch_bounds__(256)
void qkv_mma(const float* __restrict__ bq, const float* __restrict__ bk,
             const float* __restrict__ bv) {
    extern __shared__ char smem[];
    const int tid = threadIdx.x, lane = tid & 31, wid = tid >> 5;
    const int wm = (wid >> 2) * 64, wn = (wid & 3) * 32;
    const int z = blockIdx.z, h = blockIdx.x, m0 = blockIdx.y * 128, n0 = h * 128;
    const float* bias = (z == 0) ? bq : (z == 1) ? bk : bv;

    float acc[4][4][4];
    gemm_run2<64>(smem, tid,
        [&](int it) { return &g_x2[0][(size_t)m0 * H_ + it * 32]; }, (size_t)H_, (size_t)M_ * H_,
        [&](int it) { return &g_wt2[z][0][(size_t)n0 * H_ + it * 32]; }, (size_t)H_, (size_t)H_ * H_,
        acc);

    const int bb = m0 >> 11, s0 = m0 & (S_ - 1);
    if (z < 2) {
        __nv_bfloat16* base = ((z == 0) ? g_q2[0] : g_k2[0]) + (size_t)(bb * NH_ + h) * S_ * HD_;
#pragma unroll
        for (int i = 0; i < 4; ++i)
#pragma unroll
            for (int j = 0; j < 4; ++j)
#pragma unroll
                for (int hf = 0; hf < 2; ++hf) {
                    int s = s0 + wm + i * 16 + (lane >> 2) + hf * 8;
                    int d = wn + j * 8 + ((lane & 3) << 1);
                    uint32_t hh, ll;
                    split2(acc[i][j][hf * 2] + bias[n0 + d],
                           acc[i][j][hf * 2 + 1] + bias[n0 + d + 1], hh, ll);
                    *(uint32_t*)(base + (size_t)s * HD_ + d)            = hh;
                    *(uint32_t*)(base + LO_QKVA + (size_t)s * HD_ + d)  = ll;
                }
    } else {
        __nv_bfloat16* vb = g_vT2[0] + (size_t)(bb * NH_ + h) * HD_ * S_;
#pragma unroll
        for (int i = 0; i < 4; ++i)
#pragma unroll
            for (int j = 0; j < 4; ++j)
#pragma unroll
                for (int hf = 0; hf < 2; ++hf) {
                    int s = s0 + wm + i * 16 + (lane >> 2) + hf * 8;
                    int d = wn + j * 8 + ((lane & 3) << 1);
                    __nv_bfloat16 h0, l0, h1, l1;
                    split1(acc[i][j][hf * 2] + bias[n0 + d], h0, l0);
                    split1(acc[i][j][hf * 2 + 1] + bias[n0 + d + 1], h1, l1);
                    vb[(size_t)d * S_ + s]                 = h0;
                    vb[LO_QKVA + (size_t)d * S_ + s]       = l0;
                    vb[(size_t)(d + 1) * S_ + s]           = h1;
                    vb[LO_QKVA + (size_t)(d + 1) * S_ + s] = l1;
                }
    }
}

// ---------------------------------------------------------------------------
// Flash attention: fused scores + softmax + PV. grid (16 qblocks, 32 z).
// Per warp: 16 q-rows, full s and d ranges. K-block = 64 keys, double-buffered.
// SMEM: Q hi/lo [128][128] (stride 272B) | 2 stages of {Khi,Klo [64][128] s272,
//       Vhi,Vlo [128][64] s144}
// ---------------------------------------------------------------------------
static constexpr int QPL  = 128 * 272;            // 34816 per plane
static constexpr int KPL  = 64 * 272;             // 17408
static constexpr int VPL  = 128 * 144;            // 18432
static constexpr int FSTG = 2 * KPL + 2 * VPL;    // 71680
static constexpr int SOFF = 2 * QPL;              // 69632
static constexpr int SMEM_F = SOFF + 2 * FSTG;    // 212992

__device__ __forceinline__ void load_kv(uint32_t stg, const __nv_bfloat16* Kh,
                                        const __nv_bfloat16* Vh, int s0, int tid) {
#pragma unroll
    for (int i = 0; i < 4; ++i) {
        int idx = tid + (i << 8);
        {
            int r = idx >> 4, c = idx & 15;
            const __nv_bfloat16* s = Kh + (size_t)(s0 + r) * HD_ + c * 8;
            uint32_t d = stg + (uint32_t)(r * 272 + c * 16);
            CP16(d, s); CP16(d + KPL, s + LO_QKVA);
        }
        {
            int r = idx >> 3, c = idx & 7;
            const __nv_bfloat16* s = Vh + (size_t)r * S_ + s0 + c * 8;
            uint32_t d = stg + 2u * KPL + (uint32_t)(r * 144 + c * 16);
            CP16(d, s); CP16(d + VPL, s + LO_QKVA);
        }
    }
}

__global__ __launch_bounds__(256)
void flash_attn(const float* __restrict__ mask) {
    extern __shared__ char smem[];
    const int tid = threadIdx.x, lane = tid & 31, wid = tid >> 5;
    const int q0 = blockIdx.x * 128, z = blockIdx.y, bb = z >> 4;
    const uint32_t sb = smem_u32(smem);
    const __nv_bfloat16* Qh = g_q2[0] + (size_t)z * S_ * HD_;
    const __nv_bfloat16* Kh = g_k2[0] + (size_t)z * S_ * HD_;
    const __nv_bfloat16* Vh = g_vT2[0] + (size_t)z * HD_ * S_;

    // Load Q tile (hi+lo) + stage 0 K/V
#pragma unroll
    for (int i = 0; i < 8; ++i) {
        int idx = tid + (i << 8), r = idx >> 4, c = idx & 15;
        const __nv_bfloat16* s = Qh + (size_t)(q0 + r) * HD_ + c * 8;
        uint32_t d = sb + (uint32_t)(r * 272 + c * 16);
        CP16(d, s); CP16(d + QPL, s + LO_QKVA);
    }
    load_kv(sb + SOFF, Kh, Vh, 0, tid);
    CP_COMMIT(); CP_WAIT0(); __syncthreads();

    // Q fragments (resident in registers): 8 k16 steps x (hi, lo)
    uint32_t aqh[8][4], aql[8][4];
    {
        uint32_t qb = sb + (uint32_t)((wid * 16 + (lane & 15)) * 272 + (lane >> 4) * 16);
#pragma unroll
        for (int kk = 0; kk < 8; ++kk) {
            ldm4(aqh[kk], qb + (uint32_t)kk * 32);
            ldm4(aql[kk], qb + QPL + (uint32_t)kk * 32);
        }
    }

    float acc_o[16][4];
#pragma unroll
    for (int j = 0; j < 16; ++j)
#pragma unroll
        for (int e = 0; e < 4; ++e) acc_o[j][e] = 0.0f;
    float l0 = 0.0f, l1 = 0.0f, m0p = -1e30f, m1p = -1e30f;
    const float SC = 0.08838834764831845f;

    const int qr = q0 + wid * 16 + (lane >> 2);
    const float* mrow = mask + ((size_t)bb * S_ + qr) * S_ + ((lane & 3) << 1);

    const uint32_t koff = (uint32_t)(((lane & 7) + ((lane >> 4) << 3)) * 272 + ((lane >> 3) & 1) * 16);
    const uint32_t voff = (uint32_t)(((lane & 7) + ((lane >> 4) << 3)) * 144 + ((lane >> 3) & 1) * 16);

    for (int kb = 0; kb < 32; ++kb) {
        int cur = kb & 1;
        if (kb + 1 < 32) {
            load_kv(sb + SOFF + (uint32_t)(cur ^ 1) * FSTG, Kh, Vh, (kb + 1) * 64, tid);
            CP_COMMIT();
        }
        // prefetch mask fragments (hidden under S MMAs)
        float mk0[8][2], mk1[8][2];
        {
            const float* mp = mrow + kb * 64;
#pragma unroll
            for (int j = 0; j < 8; ++j) {
                float2 u = *(const float2*)(mp + j * 8);
                float2 v = *(const float2*)(mp + 8 * (size_t)S_ + j * 8);
                mk0[j][0] = u.x; mk0[j][1] = u.y;
                mk1[j][0] = v.x; mk1[j][1] = v.y;
            }
        }
        uint32_t stg = sb + SOFF + (uint32_t)cur * FSTG;

        // ---- S = Q K^T (3-term split) ----
        float ps[8][4];
#pragma unroll
        for (int j = 0; j < 8; ++j) { ps[j][0] = ps[j][1] = ps[j][2] = ps[j][3] = 0.0f; }
        uint32_t ka = stg + koff;
#pragma unroll
        for (int kk = 0; kk < 8; ++kk) {
#pragma unroll
            for (int s2 = 0; s2 < 4; ++s2) {
                uint32_t th[4], tl[4];
                ldm4(th, ka + (uint32_t)(s2 * 16 * 272) + (uint32_t)kk * 32);
                ldm4(tl, ka + KPL + (uint32_t)(s2 * 16 * 272) + (uint32_t)kk * 32);
                uint32_t b0[2] = { th[0], th[1] }, b1[2] = { th[2], th[3] };
                uint32_t c0[2] = { tl[0], tl[1] }, c1[2] = { tl[2], tl[3] };
                mma_bf16(ps[2 * s2],     aqh[kk], b0);
                mma_bf16(ps[2 * s2],     aqh[kk], c0);
                mma_bf16(ps[2 * s2],     aql[kk], b0);
                mma_bf16(ps[2 * s2 + 1], aqh[kk], b1);
                mma_bf16(ps[2 * s2 + 1], aqh[kk], c1);
                mma_bf16(ps[2 * s2 + 1], aql[kk], b1);
            }
        }

        // ---- online softmax (per-row stats live in lane quads) ----
        float mx0 = -1e30f, mx1 = -1e30f;
#pragma unroll
        for (int j = 0; j < 8; ++j) {
            ps[j][0] = ps[j][0] * SC + mk0[j][0];
            ps[j][1] = ps[j][1] * SC + mk0[j][1];
            ps[j][2] = ps[j][2] * SC + mk1[j][0];
            ps[j][3] = ps[j][3] * SC + mk1[j][1];
            mx0 = fmaxf(mx0, fmaxf(ps[j][0], ps[j][1]));
            mx1 = fmaxf(mx1, fmaxf(ps[j][2], ps[j][3]));
        }
        mx0 = fmaxf(mx0, __shfl_xor_sync(0xffffffffu, mx0, 1));
        mx0 = fmaxf(mx0, __shfl_xor_sync(0xffffffffu, mx0, 2));
        mx1 = fmaxf(mx1, __shfl_xor_sync(0xffffffffu, mx1, 1));
        mx1 = fmaxf(mx1, __shfl_xor_sync(0xffffffffu, mx1, 2));
        float mn0 = fmaxf(m0p, mx0), mn1 = fmaxf(m1p, mx1);
        float f0 = __expf(m0p - mn0), f1 = __expf(m1p - mn1);
        float sa0 = 0.0f, sa1 = 0.0f;
#pragma unroll
        for (int j = 0; j < 8; ++j) {
            ps[j][0] = __expf(ps[j][0] - mn0); sa0 += ps[j][0];
            ps[j][1] = __expf(ps[j][1] - mn0); sa0 += ps[j][1];
            ps[j][2] = __expf(ps[j][2] - mn1); sa1 += ps[j][2];
            ps[j][3] = __expf(ps[j][3] - mn1); sa1 += ps[j][3];
        }
        sa0 += __shfl_xor_sync(0xffffffffu, sa0, 1);
        sa0 += __shfl_xor_sync(0xffffffffu, sa0, 2);
        sa1 += __shfl_xor_sync(0xffffffffu, sa1, 1);
        sa1 += __shfl_xor_sync(0xffffffffu, sa1, 2);
        l0 = l0 * f0 + sa0; l1 = l1 * f1 + sa1;
        m0p = mn0; m1p = mn1;
#pragma unroll
        for (int j = 0; j < 16; ++j) {
            acc_o[j][0] *= f0; acc_o[j][1] *= f0;
            acc_o[j][2] *= f1; acc_o[j][3] *= f1;
        }

        // ---- O += P V (P fragments straight from ps registers) ----
        uint32_t va = stg + 2u * KPL + voff;
#pragma unroll
        for (int kk2 = 0; kk2 < 4; ++kk2) {
            uint32_t pah[4], pal[4];
            split2(ps[2 * kk2][0],     ps[2 * kk2][1],     pah[0], pal[0]);
            split2(ps[2 * kk2][2],     ps[2 * kk2][3],     pah[1], pal[1]);
            split2(ps[2 * kk2 + 1][0], ps[2 * kk2 + 1][1], pah[2], pal[2]);
            split2(ps[2 * kk2 + 1][2], ps[2 * kk2 + 1][3], pah[3], pal[3]);
#pragma unroll
            for (int s2 = 0; s2 < 8; ++s2) {
                uint32_t th[4], tl[4];
                ldm4(th, va + (uint32_t)(s2 * 16 * 144) + (uint32_t)kk2 * 32);
                ldm4(tl, va + VPL + (uint32_t)(s2 * 16 * 144) + (uint32_t)kk2 * 32);
                uint32_t b0[2] = { th[0], th[1] }, b1[2] = { th[2], th[3] };
                uint32_t c0[2] = { tl[0], tl[1] }, c1[2] = { tl[2], tl[3] };
                mma_bf16(acc_o[2 * s2],     pah, b0);
                mma_bf16(acc_o[2 * s2],     pah, c0);
                mma_bf16(acc_o[2 * s2],     pal, b0);
                mma_bf16(acc_o[2 * s2 + 1], pah, b1);
                mma_bf16(acc_o[2 * s2 + 1], pah, c1);
                mma_bf16(acc_o[2 * s2 + 1], pal, b1);
            }
        }
        CP_WAIT0(); __syncthreads();
    }

    // ---- epilogue: O/l -> hi/lo bf16 ----
    float i0 = 1.0f / l0, i1 = 1.0f / l1;
    __nv_bfloat16* Ah = g_at2[0] + (size_t)z * S_ * HD_;
    int sr = q0 + wid * 16 + (lane >> 2);
#pragma unroll
    for (int j2 = 0; j2 < 16; ++j2) {
        int d = j2 * 8 + ((lane & 3) << 1);
        uint32_t hh, ll;
        split2(acc_o[j2][0] * i0, acc_o[j2][1] * i0, hh, ll);
        *(uint32_t*)(Ah + (size_t)sr * HD_ + d)           = hh;
        *(uint32_t*)(Ah + LO_QKVA + (size_t)sr * HD_ + d) = ll;
        split2(acc_o[j2][2] * i1, acc_o[j2][3] * i1, hh, ll);
        *(uint32_t*)(Ah + (size_t)(sr + 8) * HD_ + d)           = hh;
        *(uint32_t*)(Ah + LO_QKVA + (size_t)(sr + 8) * HD_ + d) = ll;
    }
}

// ---------------------------------------------------------------------------
// Kernel 3: out = gather(attn) @ W_O + b_O.  grid (16, 32)
// ---------------------------------------------------------------------------
__global__ __launch_bounds__(256)
void out_mma(const float* __restrict__ bo, float* __restrict__ out) {
    extern __shared__ char smem[];
    const int tid = threadIdx.x, lane = tid & 31, wid = tid >> 5;
    const int wm = (wid >> 2) * 64, wn = (wid & 3) * 32;
    const int n0 = blockIdx.x * 128, m0 = blockIdx.y * 128;
    const int bb = m0 >> 11, s0 = m0 & (S_ - 1);

    float acc[4][4][4];
    gemm_run2<64>(smem, tid,
        [&](int it) {
            int h = it >> 2, dbase = (it & 3) * 32;
            return &g_at2[0][((size_t)(bb * NH_ + h) * S_ + s0) * HD_ + dbase];
        }, (size_t)HD_, LO_QKVA,
        [&](int it) { return &g_wt2[3][0][(size_t)n0 * H_ + it * 32]; }, (size_t)H_, (size_t)H_ * H_,
        acc);

#pragma unroll
    for (int i = 0; i < 4; ++i)
#pragma unroll
        for (int j = 0; j < 4; ++j)
#pragma unroll
            for (int hf = 0; hf < 2; ++hf) {
                int m = m0 + wm + i * 16 + (lane >> 2) + hf * 8;
                int n = n0 + wn + j * 8 + ((lane & 3) << 1);
                float2 v = make_float2(acc[i][j][hf * 2] + bo[n],
                                       acc[i][j][hf * 2 + 1] + bo[n + 1]);
                *(float2*)(out + (size_t)m * H_ + n) = v;
            }
}

// ---------------------------------------------------------------------------
// Launch
// ---------------------------------------------------------------------------
extern "C" void kernel_launch(void* const* d_in, const int* in_sizes, int n_in,
                              void* d_out, int out_size) {
    const float* batch = (const float*)d_in[0];
    const float* mask  = (const float*)d_in[1];
    const float* wq = (const float*)d_in[2]; const float* bq = (const float*)d_in[3];
    const float* wk = (const float*)d_in[4]; const float* bk = (const float*)d_in[5];
    const float* wv = (const float*)d_in[6]; const float* bv = (const float*)d_in[7];
    const float* wo = (const float*)d_in[8]; const float* bo = (const float*)d_in[9];
    float* out = (float*)d_out;

    cudaFuncSetAttribute(qkv_mma,    cudaFuncAttributeMaxDynamicSharedMemorySize, SMEM_G);
    cudaFuncSetAttribute(flash_attn, cudaFuncAttributeMaxDynamicSharedMemorySize, SMEM_F);
    cudaFuncSetAttribute(out_mma,    cudaFuncAttributeMaxDynamicSharedMemorySize, SMEM_G);

    prep_x<<<(int)((size_t)M_ * H_ / 4 / 256), 256>>>(batch);
    transpose_w<<<dim3(64, 64, 4), dim3(32, 8)>>>(wq, wk, wv, wo);
    qkv_mma<<<dim3(16, 32, 3), 256, SMEM_G>>>(bq, bk, bv);
    flash_attn<<<dim3(16, 32), 256, SMEM_F>>>(mask);
    out_mma<<<dim3(16, 32), 256, SMEM_G>>>(bo, out);
}